// round 14
// baseline (speedup 1.0000x reference)
#include <cuda_runtime.h>

// ---------------------------------------------------------------------------
// Problem constants
// ---------------------------------------------------------------------------
#define NB   16384
#define NL   16
#define NT   16384

// Output float offsets
#define SELF_W    608
#define TM_BASE   9961472
#define OP_BASE   15204352
#define OL_BASE   21495808
#define MASK_BASE 27787264
#define AMAP_BASE 27885568
#define UMAP_BASE 44662784

// Block striping: period 33 = 9 hash + 16 lidar + 8 copy; 128 periods
#define GRID_BLKS 4224
// lidar smem: 3840 weights + 2 lanes x 4504 activations
#define LANE_FLOATS 4504
#define SMEM_FLOATS (3840 + 2 * LANE_FLOATS)
#define SMEM_BYTES (SMEM_FLOATS * 4)

__constant__ float c_res[16] = {16.f, 21.f, 27.f, 36.f, 48.f, 64.f, 84.f, 111.f,
                                147.f, 194.f, 256.f, 337.f, 445.f, 588.f, 776.f, 1024.f};

__device__ __forceinline__ float lrelu(float x) { return x >= 0.f ? x : 0.01f * x; }

typedef unsigned long long u64;

__device__ __forceinline__ u64 fma2(u64 a, u64 b, u64 c) {
    u64 d;
    asm("fma.rn.f32x2 %0, %1, %2, %3;" : "=l"(d) : "l"(a), "l"(b), "l"(c));
    return d;
}
__device__ __forceinline__ float2 unpk(u64 v) {
    float x, y;
    asm("mov.b64 {%0,%1}, %2;" : "=f"(x), "=f"(y) : "l"(v));
    return make_float2(x, y);
}

struct Args {
    const float* p[30];
    float* out;
};

// ---------------------------------------------------------------------------
// Hash part (proven round-9 body, x-corner pair merge)
// ---------------------------------------------------------------------------
__device__ __forceinline__ void hash_part(int blk, const Args& A, float* sm)
{
    float* enc = sm;                       // 256*33 floats
    const int t  = threadIdx.x;
    const int gp = blk * 256 + t;

    int seg, q;
    const float* pos;
    if (gp < 16384)        { seg = 0; q = gp;          pos = A.p[0] + q * 3; }
    else if (gp < 98304)   { seg = 1; q = gp - 16384;  pos = A.p[1] + q * 3; }
    else if (gp < 196608)  { seg = 2; q = gp - 98304;  pos = A.p[2] + q * 3; }
    else                   { seg = 3; q = gp - 196608; pos = A.p[3] + q * 3; }

    const float2* table = (const float2*)A.p[13];

    const float x0 = __ldg(pos + 0), x1p = __ldg(pos + 1), x2p = __ldg(pos + 2);
    const float xn0 = fminf(fmaxf((x0  + 1.f) * 0.5f, 0.f), 1.f);
    const float xn1 = fminf(fmaxf((x1p + 1.f) * 0.5f, 0.f), 1.f);
    const float xn2 = fminf(fmaxf((x2p + 1.f) * 0.5f, 0.f), 1.f);

    #pragma unroll 2
    for (int l = 0; l < NL; l++) {
        const float r = c_res[l];
        const float s0 = xn0 * r, s1 = xn1 * r, s2 = xn2 * r;
        const float f0 = floorf(s0), f1 = floorf(s1), f2 = floorf(s2);
        const float w0 = s0 - f0, w1 = s1 - f1, w2 = s2 - f2;
        const unsigned c0 = (unsigned)f0, c1 = (unsigned)f1, c2 = (unsigned)f2;

        const unsigned h1a = c1 * 2654435761u;
        const unsigned h1b = h1a + 2654435761u;
        const unsigned h2a = c2 * 805459861u;
        const unsigned h2b = h2a + 805459861u;

        unsigned hyz[4];
        hyz[0] = h1a ^ h2a; hyz[1] = h1a ^ h2b;
        hyz[2] = h1b ^ h2a; hyz[3] = h1b ^ h2b;

        const float2* tl  = table + (size_t)l * NT;
        const float4* tl4 = (const float4*)tl;

        unsigned i0[4];
        float4 f4[4];
        #pragma unroll
        for (int m = 0; m < 4; m++) {
            i0[m] = (c0 ^ hyz[m]) & (NT - 1);
            f4[m] = __ldg(tl4 + (i0[m] >> 1));
        }

        float2 e1v[4];
        if (c0 & 1u) {
            #pragma unroll
            for (int m = 0; m < 4; m++) {
                const unsigned i1 = ((c0 + 1u) ^ hyz[m]) & (NT - 1);
                e1v[m] = __ldg(tl + i1);
            }
        } else {
            #pragma unroll
            for (int m = 0; m < 4; m++) {
                e1v[m] = (i0[m] & 1u) ? make_float2(f4[m].x, f4[m].y)
                                      : make_float2(f4[m].z, f4[m].w);
            }
        }

        float a0 = 0.f, a1 = 0.f;
        const float wx0 = 1.f - w0;
        #pragma unroll
        for (int m = 0; m < 4; m++) {
            const float wy = (m & 2) ? w1 : 1.f - w1;
            const float wz = (m & 1) ? w2 : 1.f - w2;
            const float wyz = wy * wz;
            const float2 e0 = (i0[m] & 1u) ? make_float2(f4[m].z, f4[m].w)
                                           : make_float2(f4[m].x, f4[m].y);
            const float wt0 = wyz * wx0;
            const float wt1 = wyz * w0;
            a0 = fmaf(wt0, e0.x,      a0);
            a1 = fmaf(wt0, e0.y,      a1);
            a0 = fmaf(wt1, e1v[m].x,  a0);
            a1 = fmaf(wt1, e1v[m].y,  a1);
        }
        enc[t * 33 + 2 * l]     = a0;
        enc[t * 33 + 2 * l + 1] = a1;
    }
    __syncthreads();

    float* out = A.out;
    if (seg == 0) {
        const float* self_vec = A.p[4];
        const int q0 = blk * 256;
        for (int i = t; i < 256 * 96; i += 256) {
            const int p = i / 96;
            const int c = i - p * 96;
            const int qq = q0 + p;
            float v = (c < 32) ? enc[p * 33 + c]
                               : __ldg(self_vec + qq * 64 + (c - 32));
            out[qq * SELF_W + c] = v;
        }
    } else {
        const float* aux = (seg == 1) ? A.p[7] : (seg == 2 ? A.p[8] : A.p[9]);
        const int base   = (seg == 1) ? TM_BASE : (seg == 2 ? OP_BASE : OL_BASE);
        const int seg0   = (seg == 1) ? 16384   : (seg == 2 ? 98304   : 196608);
        const int q0     = blk * 256 - seg0;
        for (int i = t; i < 256 * 64; i += 256) {
            const int p = i >> 6;
            const int c = i & 63;
            const int qq = q0 + p;
            float v = (c < 32) ? enc[p * 33 + c]
                               : __ldg(aux + qq * 32 + (c - 32));
            out[base + qq * 64 + c] = v;
        }
    }
}

// ---------------------------------------------------------------------------
// Lidar part: even/odd split layouts (round-12) + position-pair blocking.
// Each thread computes 2 adjacent positions x half co-set -> weight rows
// reused twice. Layout per lane (4504 floats):
//   X1 per q (stride 1320): X1e[32][20] at +0, X1o[32][20] at +656
//   X2 at +2640 per q (stride 672): X2e[16][20] at +0, X2o[16][20] at +336
//   X3 at +3984 [2][256] | RED at +4496 [2][4]
// ---------------------------------------------------------------------------
__device__ __forceinline__ void lidar_part(int lb, const Args& A, float* sm)
{
    const int t = threadIdx.x;
    float* W = sm;

    for (int i = t; i < 3840; i += 256) {
        float v;
        if (i < 768) {
            int q = i / 384, r = i % 384, co = r / 24, k = r % 24;
            v = __ldg((q ? A.p[22] : A.p[14]) + k * 16 + co);
        } else if (i < 2304) {
            int j = i - 768, q = j / 768, r = j % 768, co = r / 48, k = r % 48;
            v = __ldg((q ? A.p[24] : A.p[16]) + k * 16 + co);
        } else {
            int j = i - 2304, q = j / 768, r = j % 768, co = r / 48, k = r % 48;
            v = __ldg((q ? A.p[26] : A.p[18]) + k * 16 + co);
        }
        W[i] = v;
    }
    __syncthreads();

    const int s = t >> 7;          // batch lane
    const int l = t & 127;
    float* XB  = sm + 3840 + s * LANE_FLOATS;
    float* X3  = XB + 3984;
    float* RED = XB + 4496;

    const ulonglong2* W2 = (const ulonglong2*)W;

    const float* fl_in = A.p[5];
    const float* rl_in = A.p[6];
    float* out = A.out;

    #pragma unroll 1
    for (int it = 0; it < 4; ++it) {
        const int b = lb * 8 + it * 2 + s;

        // ---- conv1: (q, og:32, cg:2) -> pos {2og,2og+1} x co {8cg..8cg+7} ----
        {
            const int q = l >> 6, rem = l & 63, og = rem >> 1, cg = rem & 1;
            const float* lid = (q ? rl_in : fl_in) + (size_t)b * 1024;
            u64 acc[16];
            #pragma unroll
            for (int i = 0; i < 16; i++) acc[i] = 0ull;

            #pragma unroll
            for (int j = 0; j < 3; j++) {
                const int t0 = 4 * og + j;
                const int t1 = 4 * og + 2 + j;
                const bool ok1 = t1 < 128;
                u64 xa[4], xb[4];
                #pragma unroll
                for (int a = 0; a < 4; a++) {
                    xa[a] = *(const u64*)(lid + a * 256 + t0 * 2);
                    xb[a] = ok1 ? *(const u64*)(lid + a * 256 + t1 * 2) : 0ull;
                }
                #pragma unroll
                for (int ci = 0; ci < 8; ci++) {
                    const int co = cg * 8 + ci;
                    const ulonglong2* wr = W2 + q * 96 + co * 6 + j * 2;
                    const ulonglong2 wA = wr[0], wB = wr[1];
                    u64 a0 = acc[ci * 2], a1 = acc[ci * 2 + 1];
                    a0 = fma2(xa[0], wA.x, a0); a1 = fma2(xb[0], wA.x, a1);
                    a0 = fma2(xa[1], wA.y, a0); a1 = fma2(xb[1], wA.y, a1);
                    a0 = fma2(xa[2], wB.x, a0); a1 = fma2(xb[2], wB.x, a1);
                    a0 = fma2(xa[3], wB.y, a0); a1 = fma2(xb[3], wB.y, a1);
                    acc[ci * 2] = a0; acc[ci * 2 + 1] = a1;
                }
            }
            const float* bp = q ? A.p[23] : A.p[15];
            float* xw0 = XB + q * 1320 +       og * 20 + cg * 8;   // pos 2og   -> X1e[og]
            float* xw1 = XB + q * 1320 + 656 + og * 20 + cg * 8;   // pos 2og+1 -> X1o[og]
            #pragma unroll
            for (int g = 0; g < 2; g++) {
                float y0[4], y1[4];
                #pragma unroll
                for (int k = 0; k < 4; k++) {
                    const int ci = g * 4 + k;
                    const float bb = __ldg(bp + cg * 8 + ci);
                    float2 p0 = unpk(acc[ci * 2]);
                    float2 p1 = unpk(acc[ci * 2 + 1]);
                    y0[k] = lrelu(bb + (p0.x + p0.y));
                    y1[k] = lrelu(bb + (p1.x + p1.y));
                }
                *(float4*)(xw0 + 4 * g) = make_float4(y0[0], y0[1], y0[2], y0[3]);
                *(float4*)(xw1 + 4 * g) = make_float4(y1[0], y1[1], y1[2], y1[3]);
            }
        }
        __syncthreads();

        // ---- conv2: (q, og:16, cg:4) -> pos {2og,2og+1} x co {4cg..4cg+3} ----
        // tap rows: j=0: X1e[2og] / X1e[2og+1]; j=1: X1o[2og] / X1o[2og+1];
        //           j=2: X1e[2og+1] / X1e[2og+2] (guard)
        {
            const int q = l >> 6, rem = l & 63, og = rem & 15, cg = rem >> 4;
            const float* X1q = XB + q * 1320;
            u64 acc[8];
            #pragma unroll
            for (int i = 0; i < 8; i++) acc[i] = 0ull;

            #pragma unroll
            for (int j = 0; j < 3; j++) {
                const float* rowA_f = (j == 0) ? (X1q + (2 * og) * 20)
                                   : (j == 1) ? (X1q + 656 + (2 * og) * 20)
                                              : (X1q + (2 * og + 1) * 20);
                const float* rowB_f = (j == 0) ? (X1q + (2 * og + 1) * 20)
                                   : (j == 1) ? (X1q + 656 + (2 * og + 1) * 20)
                                              : (X1q + (2 * og + 2) * 20);
                const bool okB = (j < 2) || (2 * og + 2 < 32);
                const ulonglong2* sA = (const ulonglong2*)rowA_f;
                const ulonglong2* sB = (const ulonglong2*)rowB_f;
                u64 xa[8], xb[8];
                #pragma unroll
                for (int v = 0; v < 4; v++) {
                    ulonglong2 ua = sA[v];
                    ulonglong2 ub = okB ? sB[v] : make_ulonglong2(0ull, 0ull);
                    xa[2*v] = ua.x; xa[2*v+1] = ua.y;
                    xb[2*v] = ub.x; xb[2*v+1] = ub.y;
                }
                #pragma unroll
                for (int ci = 0; ci < 4; ci++) {
                    const int co = cg * 4 + ci;
                    const ulonglong2* wr = W2 + 192 + q * 192 + co * 12 + j * 4;
                    u64 a0 = acc[ci * 2], a1 = acc[ci * 2 + 1];
                    #pragma unroll
                    for (int v = 0; v < 4; v++) {
                        const ulonglong2 w = wr[v];
                        a0 = fma2(xa[2*v],   w.x, a0); a1 = fma2(xb[2*v],   w.x, a1);
                        a0 = fma2(xa[2*v+1], w.y, a0); a1 = fma2(xb[2*v+1], w.y, a1);
                    }
                    acc[ci * 2] = a0; acc[ci * 2 + 1] = a1;
                }
            }
            const float* bp = q ? A.p[25] : A.p[17];
            float y0[4], y1[4];
            #pragma unroll
            for (int ci = 0; ci < 4; ci++) {
                const float bb = __ldg(bp + cg * 4 + ci);
                float2 p0 = unpk(acc[ci * 2]);
                float2 p1 = unpk(acc[ci * 2 + 1]);
                y0[ci] = lrelu(bb + (p0.x + p0.y));
                y1[ci] = lrelu(bb + (p1.x + p1.y));
            }
            float* xw0 = XB + 2640 + q * 672 +       og * 20 + cg * 4;  // pos 2og   -> X2e[og]
            float* xw1 = XB + 2640 + q * 672 + 336 + og * 20 + cg * 4;  // pos 2og+1 -> X2o[og]
            *(float4*)xw0 = make_float4(y0[0], y0[1], y0[2], y0[3]);
            *(float4*)xw1 = make_float4(y1[0], y1[1], y1[2], y1[3]);
        }
        __syncthreads();

        // ---- conv3: (q, og:8, cg:8) -> pos {2og,2og+1} x co {2cg,2cg+1} ----
        {
            const int q = l >> 6, rem = l & 63, og = rem & 7, cg = rem >> 3;
            const float* X2q = XB + 2640 + q * 672;
            u64 acc[4];
            #pragma unroll
            for (int i = 0; i < 4; i++) acc[i] = 0ull;

            #pragma unroll
            for (int j = 0; j < 3; j++) {
                const float* rowA_f = (j == 0) ? (X2q + (2 * og) * 20)
                                   : (j == 1) ? (X2q + 336 + (2 * og) * 20)
                                              : (X2q + (2 * og + 1) * 20);
                const float* rowB_f = (j == 0) ? (X2q + (2 * og + 1) * 20)
                                   : (j == 1) ? (X2q + 336 + (2 * og + 1) * 20)
                                              : (X2q + (2 * og + 2) * 20);
                const bool okB = (j < 2) || (2 * og + 2 < 16);
                const ulonglong2* sA = (const ulonglong2*)rowA_f;
                const ulonglong2* sB = (const ulonglong2*)rowB_f;
                u64 xa[8], xb[8];
                #pragma unroll
                for (int v = 0; v < 4; v++) {
                    ulonglong2 ua = sA[v];
                    ulonglong2 ub = okB ? sB[v] : make_ulonglong2(0ull, 0ull);
                    xa[2*v] = ua.x; xa[2*v+1] = ua.y;
                    xb[2*v] = ub.x; xb[2*v+1] = ub.y;
                }
                #pragma unroll
                for (int ci = 0; ci < 2; ci++) {
                    const int co = cg * 2 + ci;
                    const ulonglong2* wr = W2 + 576 + q * 192 + co * 12 + j * 4;
                    u64 a0 = acc[ci * 2], a1 = acc[ci * 2 + 1];
                    #pragma unroll
                    for (int v = 0; v < 4; v++) {
                        const ulonglong2 w = wr[v];
                        a0 = fma2(xa[2*v],   w.x, a0); a1 = fma2(xb[2*v],   w.x, a1);
                        a0 = fma2(xa[2*v+1], w.y, a0); a1 = fma2(xb[2*v+1], w.y, a1);
                    }
                    acc[ci * 2] = a0; acc[ci * 2 + 1] = a1;
                }
            }
            const float* bp = q ? A.p[27] : A.p[19];
            float y0[2], y1[2];
            #pragma unroll
            for (int ci = 0; ci < 2; ci++) {
                const float bb = __ldg(bp + cg * 2 + ci);
                float2 p0 = unpk(acc[ci * 2]);
                float2 p1 = unpk(acc[ci * 2 + 1]);
                y0[ci] = bb + (p0.x + p0.y);
                y1[ci] = bb + (p1.x + p1.y);
            }
            *(float2*)(X3 + q * 256 + (2 * og)     * 16 + cg * 2) = make_float2(y0[0], y0[1]);
            *(float2*)(X3 + q * 256 + (2 * og + 1) * 16 + cg * 2) = make_float2(y1[0], y1[1]);
        }
        __syncthreads();

        // ---- LayerNorm(256) + lrelu ----
        {
            const int q = l >> 6, u = l & 63;
            float v[4];
            #pragma unroll
            for (int i = 0; i < 4; i++) v[i] = X3[q * 256 + u + 64 * i];
            float ssum  = v[0] + v[1] + v[2] + v[3];
            float ssq   = v[0]*v[0] + v[1]*v[1] + v[2]*v[2] + v[3]*v[3];
            #pragma unroll
            for (int off = 16; off; off >>= 1) {
                ssum += __shfl_xor_sync(0xffffffffu, ssum, off);
                ssq  += __shfl_xor_sync(0xffffffffu, ssq,  off);
            }
            const int w2 = (l >> 5) & 1;
            if ((l & 31) == 0) { RED[q*4 + w2*2] = ssum; RED[q*4 + w2*2 + 1] = ssq; }
            __syncthreads();
            const float st  = RED[q*4]     + RED[q*4 + 2];
            const float sst = RED[q*4 + 1] + RED[q*4 + 3];
            const float mu  = st * (1.f / 256.f);
            const float var = sst * (1.f / 256.f) - mu * mu;
            const float rstd = rsqrtf(var + 1e-6f);
            const float* gp  = q ? A.p[28] : A.p[20];
            const float* bep = q ? A.p[29] : A.p[21];
            float* ob = out + (size_t)b * SELF_W + 96 + q * 256;
            #pragma unroll
            for (int i = 0; i < 4; i++) {
                const int idx = u + 64 * i;
                const float y = (v[i] - mu) * rstd * __ldg(gp + idx) + __ldg(bep + idx);
                ob[idx] = lrelu(y);
            }
        }
    }
}

// ---------------------------------------------------------------------------
// Copy part
// ---------------------------------------------------------------------------
__device__ __forceinline__ void copy_part(int cb, const Args& A)
{
    const float4* ms = (const float4*)A.p[10];
    const float4* am = (const float4*)A.p[11];
    const float4* um = (const float4*)A.p[12];
    float4* out = (float4*)A.out;
    const int t = threadIdx.x;
    const int total = 24576 + 4194304 + 4194304;   // 8413184

    for (int i = cb * 256 + t; i < total; i += 1024 * 256) {
        float4 v; int o;
        if (i < 24576) {
            v = __ldg(ms + i);                      o = MASK_BASE / 4 + i;
        } else if (i < 24576 + 4194304) {
            const int j = i - 24576;
            v = __ldg(am + j);                      o = AMAP_BASE / 4 + j;
        } else {
            const int j = i - (24576 + 4194304);
            v = __ldg(um + j);                      o = UMAP_BASE / 4 + j;
        }
        out[o] = v;
    }
}

// ---------------------------------------------------------------------------
// Fused kernel: period-33 block striping (9 hash / 16 lidar / 8 copy).
// ---------------------------------------------------------------------------
__global__ void __launch_bounds__(256, 3)
fused_kernel(Args A)
{
    extern __shared__ float sm[];
    const int b = blockIdx.x;
    const int period = b / 33;
    const int r = b - period * 33;

    if (r < 9) {
        hash_part(period * 9 + r, A, sm);
    } else if (r < 25) {
        lidar_part(period * 16 + (r - 9), A, sm);
    } else {
        copy_part(period * 8 + (r - 25), A);
    }
}

// ---------------------------------------------------------------------------
// Launch
// ---------------------------------------------------------------------------
extern "C" void kernel_launch(void* const* d_in, const int* in_sizes, int n_in,
                              void* d_out, int out_size)
{
    (void)in_sizes; (void)n_in; (void)out_size;

    static bool attr_done = false;
    if (!attr_done) {
        cudaFuncSetAttribute(fused_kernel,
                             cudaFuncAttributeMaxDynamicSharedMemorySize, SMEM_BYTES);
        attr_done = true;
    }

    Args A;
    for (int i = 0; i < 30; i++) A.p[i] = (const float*)d_in[i];
    A.out = (float*)d_out;

    fused_kernel<<<GRID_BLKS, 256, SMEM_BYTES>>>(A);
}

// round 15
// speedup vs baseline: 1.1688x; 1.1688x over previous
#include <cuda_runtime.h>

// ---------------------------------------------------------------------------
// Problem constants
// ---------------------------------------------------------------------------
#define NB   16384
#define NL   16
#define NT   16384

// Output float offsets
#define SELF_W    608
#define TM_BASE   9961472
#define OP_BASE   15204352
#define OL_BASE   21495808
#define MASK_BASE 27787264
#define AMAP_BASE 27885568
#define UMAP_BASE 44662784

// Block striping: period 33 = 9 hash + 16 lidar + 8 copy; 128 periods
#define GRID_BLKS 4224
// lidar smem: 3840 weights + 2 lanes x 4504 activations = 51392 B
#define LANE_FLOATS 4504
#define SMEM_FLOATS (3840 + 2 * LANE_FLOATS)
#define SMEM_BYTES (SMEM_FLOATS * 4)

// TMA copy: 32KB staging buffer at smem offset 0, mbarrier at +32768
#define COPY_BUF_BYTES 32768u

__constant__ float c_res[16] = {16.f, 21.f, 27.f, 36.f, 48.f, 64.f, 84.f, 111.f,
                                147.f, 194.f, 256.f, 337.f, 445.f, 588.f, 776.f, 1024.f};

__device__ __forceinline__ float lrelu(float x) { return x >= 0.f ? x : 0.01f * x; }

typedef unsigned long long u64;

__device__ __forceinline__ u64 fma2(u64 a, u64 b, u64 c) {
    u64 d;
    asm("fma.rn.f32x2 %0, %1, %2, %3;" : "=l"(d) : "l"(a), "l"(b), "l"(c));
    return d;
}
__device__ __forceinline__ float2 unpk(u64 v) {
    float x, y;
    asm("mov.b64 {%0,%1}, %2;" : "=f"(x), "=f"(y) : "l"(v));
    return make_float2(x, y);
}
__device__ __forceinline__ unsigned smem_u32(const void* p) {
    unsigned a;
    asm("{ .reg .u64 t; cvta.to.shared.u64 t, %1; cvt.u32.u64 %0, t; }"
        : "=r"(a) : "l"(p));
    return a;
}

struct Args {
    const float* p[30];
    float* out;
};

// ---------------------------------------------------------------------------
// Hash part (proven round-9/12 body, x-corner pair merge)
// ---------------------------------------------------------------------------
__device__ __forceinline__ void hash_part(int blk, const Args& A, float* sm)
{
    float* enc = sm;                       // 256*33 floats
    const int t  = threadIdx.x;
    const int gp = blk * 256 + t;

    int seg, q;
    const float* pos;
    if (gp < 16384)        { seg = 0; q = gp;          pos = A.p[0] + q * 3; }
    else if (gp < 98304)   { seg = 1; q = gp - 16384;  pos = A.p[1] + q * 3; }
    else if (gp < 196608)  { seg = 2; q = gp - 98304;  pos = A.p[2] + q * 3; }
    else                   { seg = 3; q = gp - 196608; pos = A.p[3] + q * 3; }

    const float2* table = (const float2*)A.p[13];

    const float x0 = __ldg(pos + 0), x1p = __ldg(pos + 1), x2p = __ldg(pos + 2);
    const float xn0 = fminf(fmaxf((x0  + 1.f) * 0.5f, 0.f), 1.f);
    const float xn1 = fminf(fmaxf((x1p + 1.f) * 0.5f, 0.f), 1.f);
    const float xn2 = fminf(fmaxf((x2p + 1.f) * 0.5f, 0.f), 1.f);

    #pragma unroll 2
    for (int l = 0; l < NL; l++) {
        const float r = c_res[l];
        const float s0 = xn0 * r, s1 = xn1 * r, s2 = xn2 * r;
        const float f0 = floorf(s0), f1 = floorf(s1), f2 = floorf(s2);
        const float w0 = s0 - f0, w1 = s1 - f1, w2 = s2 - f2;
        const unsigned c0 = (unsigned)f0, c1 = (unsigned)f1, c2 = (unsigned)f2;

        const unsigned h1a = c1 * 2654435761u;
        const unsigned h1b = h1a + 2654435761u;
        const unsigned h2a = c2 * 805459861u;
        const unsigned h2b = h2a + 805459861u;

        unsigned hyz[4];
        hyz[0] = h1a ^ h2a; hyz[1] = h1a ^ h2b;
        hyz[2] = h1b ^ h2a; hyz[3] = h1b ^ h2b;

        const float2* tl  = table + (size_t)l * NT;
        const float4* tl4 = (const float4*)tl;

        unsigned i0[4];
        float4 f4[4];
        #pragma unroll
        for (int m = 0; m < 4; m++) {
            i0[m] = (c0 ^ hyz[m]) & (NT - 1);
            f4[m] = __ldg(tl4 + (i0[m] >> 1));
        }

        float2 e1v[4];
        if (c0 & 1u) {
            #pragma unroll
            for (int m = 0; m < 4; m++) {
                const unsigned i1 = ((c0 + 1u) ^ hyz[m]) & (NT - 1);
                e1v[m] = __ldg(tl + i1);
            }
        } else {
            #pragma unroll
            for (int m = 0; m < 4; m++) {
                e1v[m] = (i0[m] & 1u) ? make_float2(f4[m].x, f4[m].y)
                                      : make_float2(f4[m].z, f4[m].w);
            }
        }

        float a0 = 0.f, a1 = 0.f;
        const float wx0 = 1.f - w0;
        #pragma unroll
        for (int m = 0; m < 4; m++) {
            const float wy = (m & 2) ? w1 : 1.f - w1;
            const float wz = (m & 1) ? w2 : 1.f - w2;
            const float wyz = wy * wz;
            const float2 e0 = (i0[m] & 1u) ? make_float2(f4[m].z, f4[m].w)
                                           : make_float2(f4[m].x, f4[m].y);
            const float wt0 = wyz * wx0;
            const float wt1 = wyz * w0;
            a0 = fmaf(wt0, e0.x,      a0);
            a1 = fmaf(wt0, e0.y,      a1);
            a0 = fmaf(wt1, e1v[m].x,  a0);
            a1 = fmaf(wt1, e1v[m].y,  a1);
        }
        enc[t * 33 + 2 * l]     = a0;
        enc[t * 33 + 2 * l + 1] = a1;
    }
    __syncthreads();

    float* out = A.out;
    if (seg == 0) {
        const float* self_vec = A.p[4];
        const int q0 = blk * 256;
        for (int i = t; i < 256 * 96; i += 256) {
            const int p = i / 96;
            const int c = i - p * 96;
            const int qq = q0 + p;
            float v = (c < 32) ? enc[p * 33 + c]
                               : __ldg(self_vec + qq * 64 + (c - 32));
            out[qq * SELF_W + c] = v;
        }
    } else {
        const float* aux = (seg == 1) ? A.p[7] : (seg == 2 ? A.p[8] : A.p[9]);
        const int base   = (seg == 1) ? TM_BASE : (seg == 2 ? OP_BASE : OL_BASE);
        const int seg0   = (seg == 1) ? 16384   : (seg == 2 ? 98304   : 196608);
        const int q0     = blk * 256 - seg0;
        for (int i = t; i < 256 * 64; i += 256) {
            const int p = i >> 6;
            const int c = i & 63;
            const int qq = q0 + p;
            float v = (c < 32) ? enc[p * 33 + c]
                               : __ldg(aux + qq * 32 + (c - 32));
            out[base + qq * 64 + c] = v;
        }
    }
}

// ---------------------------------------------------------------------------
// Lidar part (proven round-12 body): even/odd split activation layouts,
// one position per thread, smem weights via LDS.128.
// Per lane (4504 floats):
//   X1 per q (stride 1320): X1e[32][20] at +0, X1o[32][20] at +656
//   X2 at +2640 per q (stride 672): X2e[16][20] at +0, X2o[16][20] at +336
//   X3 at +3984 [2][256] | RED at +4496 [2][4]
// ---------------------------------------------------------------------------
__device__ __forceinline__ void lidar_part(int lb, const Args& A, float* sm)
{
    const int t = threadIdx.x;
    float* W = sm;

    for (int i = t; i < 3840; i += 256) {
        float v;
        if (i < 768) {
            int q = i / 384, r = i % 384, co = r / 24, k = r % 24;
            v = __ldg((q ? A.p[22] : A.p[14]) + k * 16 + co);
        } else if (i < 2304) {
            int j = i - 768, q = j / 768, r = j % 768, co = r / 48, k = r % 48;
            v = __ldg((q ? A.p[24] : A.p[16]) + k * 16 + co);
        } else {
            int j = i - 2304, q = j / 768, r = j % 768, co = r / 48, k = r % 48;
            v = __ldg((q ? A.p[26] : A.p[18]) + k * 16 + co);
        }
        W[i] = v;
    }
    __syncthreads();

    const int s = t >> 7;          // batch lane
    const int l = t & 127;
    float* XB  = sm + 3840 + s * LANE_FLOATS;
    float* X3  = XB + 3984;
    float* RED = XB + 4496;

    const ulonglong2* W2 = (const ulonglong2*)W;

    const float* fl_in = A.p[5];
    const float* rl_in = A.p[6];
    float* out = A.out;

    #pragma unroll 1
    for (int it = 0; it < 4; ++it) {
        const int b = lb * 8 + it * 2 + s;

        // ---- conv1: thread = (q, o:64); writes split X1 ----
        {
            const int q = l >> 6, o = l & 63;
            const float* lid = (q ? rl_in : fl_in) + (size_t)b * 1024;
            u64 xp[12];
            #pragma unroll
            for (int j = 0; j < 3; j++) {
                const int p2 = 2 * o + j;
                const bool ok = p2 < 128;
                #pragma unroll
                for (int a = 0; a < 4; a++)
                    xp[j * 4 + a] = ok ? *(const u64*)(lid + a * 256 + p2 * 2) : 0ull;
            }
            const float* bp = q ? A.p[23] : A.p[15];
            float yv[16];
            #pragma unroll
            for (int co = 0; co < 16; co++) {
                const ulonglong2* wr = W2 + q * 96 + co * 6;
                u64 acc = 0ull;
                #pragma unroll
                for (int v = 0; v < 6; v++) {
                    const ulonglong2 w = wr[v];
                    acc = fma2(xp[2*v],     w.x, acc);
                    acc = fma2(xp[2*v + 1], w.y, acc);
                }
                float2 ab = unpk(acc);
                yv[co] = lrelu(__ldg(bp + co) + (ab.x + ab.y));
            }
            float* xw = XB + q * 1320 + (o & 1) * 656 + (o >> 1) * 20;
            #pragma unroll
            for (int v = 0; v < 4; v++)
                *(float4*)(xw + 4 * v) = make_float4(yv[4*v], yv[4*v+1], yv[4*v+2], yv[4*v+3]);
        }
        __syncthreads();

        // ---- conv2: thread = (q, h:2, o:32); split X1 reads, split X2 write ----
        {
            const int q = l >> 6, rem = l & 63, h = rem >> 5, o = rem & 31;
            const float* X1q = XB + q * 1320;
            u64 acc[8] = {0ull,0ull,0ull,0ull,0ull,0ull,0ull,0ull};
            #pragma unroll
            for (int j = 0; j < 3; j++) {
                // tap row: j=0 -> X1e[o]; j=1 -> X1o[o]; j=2 -> X1e[o+1]
                const float* src_f = (j == 0) ? (X1q + o * 20)
                                  : (j == 1) ? (X1q + 656 + o * 20)
                                             : (X1q + (o + 1) * 20);
                const bool ok = (j < 2) || (o + 1 < 32);
                const ulonglong2* src = (const ulonglong2*)src_f;
                u64 xq[8];
                #pragma unroll
                for (int v = 0; v < 4; v++) {
                    ulonglong2 u = ok ? src[v] : make_ulonglong2(0ull, 0ull);
                    xq[2*v]     = u.x;
                    xq[2*v + 1] = u.y;
                }
                #pragma unroll
                for (int ci = 0; ci < 8; ci++) {
                    const int co = h * 8 + ci;
                    const ulonglong2* wr = W2 + 192 + q * 192 + co * 12 + j * 4;
                    #pragma unroll
                    for (int v = 0; v < 4; v++) {
                        const ulonglong2 w = wr[v];
                        acc[ci] = fma2(xq[2*v],     w.x, acc[ci]);
                        acc[ci] = fma2(xq[2*v + 1], w.y, acc[ci]);
                    }
                }
            }
            const float* bp = q ? A.p[25] : A.p[17];
            float yv[8];
            #pragma unroll
            for (int ci = 0; ci < 8; ci++) {
                float2 ab = unpk(acc[ci]);
                yv[ci] = lrelu(__ldg(bp + h * 8 + ci) + (ab.x + ab.y));
            }
            float* xw = XB + 2640 + q * 672 + (o & 1) * 336 + (o >> 1) * 20 + h * 8;
            *(float4*)xw       = make_float4(yv[0], yv[1], yv[2], yv[3]);
            *(float4*)(xw + 4) = make_float4(yv[4], yv[5], yv[6], yv[7]);
        }
        __syncthreads();

        // ---- conv3: thread = (q, qr:4, o:16); split X2 reads; no activation ----
        {
            const int q = l >> 6, rem = l & 63, o = rem & 15, qr = rem >> 4;
            const float* X2q = XB + 2640 + q * 672;
            u64 acc[4] = {0ull,0ull,0ull,0ull};
            #pragma unroll
            for (int j = 0; j < 3; j++) {
                const float* src_f = (j == 0) ? (X2q + o * 20)
                                  : (j == 1) ? (X2q + 336 + o * 20)
                                             : (X2q + (o + 1) * 20);
                const bool ok = (j < 2) || (o + 1 < 16);
                const ulonglong2* src = (const ulonglong2*)src_f;
                u64 xq[8];
                #pragma unroll
                for (int v = 0; v < 4; v++) {
                    ulonglong2 u = ok ? src[v] : make_ulonglong2(0ull, 0ull);
                    xq[2*v]     = u.x;
                    xq[2*v + 1] = u.y;
                }
                #pragma unroll
                for (int ci = 0; ci < 4; ci++) {
                    const int co = qr * 4 + ci;
                    const ulonglong2* wr = W2 + 576 + q * 192 + co * 12 + j * 4;
                    #pragma unroll
                    for (int v = 0; v < 4; v++) {
                        const ulonglong2 w = wr[v];
                        acc[ci] = fma2(xq[2*v],     w.x, acc[ci]);
                        acc[ci] = fma2(xq[2*v + 1], w.y, acc[ci]);
                    }
                }
            }
            const float* bp = q ? A.p[27] : A.p[19];
            float yv[4];
            #pragma unroll
            for (int ci = 0; ci < 4; ci++) {
                float2 ab = unpk(acc[ci]);
                yv[ci] = __ldg(bp + qr * 4 + ci) + (ab.x + ab.y);
            }
            *(float4*)(X3 + q * 256 + o * 16 + qr * 4)
                = make_float4(yv[0], yv[1], yv[2], yv[3]);
        }
        __syncthreads();

        // ---- LayerNorm(256) + lrelu ----
        {
            const int q = l >> 6, u = l & 63;
            float v[4];
            #pragma unroll
            for (int i = 0; i < 4; i++) v[i] = X3[q * 256 + u + 64 * i];
            float ssum  = v[0] + v[1] + v[2] + v[3];
            float ssq   = v[0]*v[0] + v[1]*v[1] + v[2]*v[2] + v[3]*v[3];
            #pragma unroll
            for (int off = 16; off; off >>= 1) {
                ssum += __shfl_xor_sync(0xffffffffu, ssum, off);
                ssq  += __shfl_xor_sync(0xffffffffu, ssq,  off);
            }
            const int w2 = (l >> 5) & 1;
            if ((l & 31) == 0) { RED[q*4 + w2*2] = ssum; RED[q*4 + w2*2 + 1] = ssq; }
            __syncthreads();
            const float st  = RED[q*4]     + RED[q*4 + 2];
            const float sst = RED[q*4 + 1] + RED[q*4 + 3];
            const float mu  = st * (1.f / 256.f);
            const float var = sst * (1.f / 256.f) - mu * mu;
            const float rstd = rsqrtf(var + 1e-6f);
            const float* gp  = q ? A.p[28] : A.p[20];
            const float* bep = q ? A.p[29] : A.p[21];
            float* ob = out + (size_t)b * SELF_W + 96 + q * 256;
            #pragma unroll
            for (int i = 0; i < 4; i++) {
                const int idx = u + 64 * i;
                const float y = (v[i] - mu) * rstd * __ldg(gp + idx) + __ldg(bep + idx);
                ob[idx] = lrelu(y);
            }
        }
    }
}

// ---------------------------------------------------------------------------
// Copy part via 1D TMA bulk: global -> smem -> global, 32KB chunks.
// Flat byte space: [0,393216) masks | [393216,67502080) amap
//                  | [67502080,134610944) umap. 1024 blocks x 131456 B each.
// One elected thread drives; zero per-lane LSU traffic.
// ---------------------------------------------------------------------------
__device__ __forceinline__ void copy_part(int cb, const Args& A, float* sm)
{
    if (threadIdx.x != 0) return;

    const u64 R0 = 393216ull;
    const u64 R1 = 67502080ull;
    const u64 CHUNK = 131456ull;

    const char* s_ms = (const char*)A.p[10];
    const char* s_am = (const char*)A.p[11];
    const char* s_um = (const char*)A.p[12];
    char* outb = (char*)A.out;

    unsigned buf  = smem_u32(sm);
    unsigned mbar = buf + COPY_BUF_BYTES;

    asm volatile("mbarrier.init.shared.b64 [%0], 1;" :: "r"(mbar) : "memory");
    asm volatile("fence.proxy.async.shared::cta;" ::: "memory");

    unsigned phase = 0;
    u64 p0 = (u64)cb * CHUNK;
    const u64 p_end = p0 + CHUNK;

    while (p0 < p_end) {
        const char* src;
        char* dst;
        u64 rend;
        if (p0 < R0) {
            src = s_ms + p0;
            dst = outb + (u64)MASK_BASE * 4 + p0;
            rend = R0;
        } else if (p0 < R1) {
            src = s_am + (p0 - R0);
            dst = outb + (u64)AMAP_BASE * 4 + (p0 - R0);
            rend = R1;
        } else {
            src = s_um + (p0 - R1);
            dst = outb + (u64)UMAP_BASE * 4 + (p0 - R1);
            rend = 134610944ull;
        }
        u64 nn = p_end < rend ? p_end - p0 : rend - p0;
        if (nn > COPY_BUF_BYTES) nn = COPY_BUF_BYTES;
        const unsigned n = (unsigned)nn;

        asm volatile("mbarrier.arrive.expect_tx.shared.b64 _, [%0], %1;"
                     :: "r"(mbar), "r"(n) : "memory");
        asm volatile("cp.async.bulk.shared::cta.global.mbarrier::complete_tx::bytes "
                     "[%0], [%1], %2, [%3];"
                     :: "r"(buf), "l"(src), "r"(n), "r"(mbar) : "memory");
        // wait for load completion
        unsigned done;
        do {
            asm volatile("{ .reg .pred p; "
                         "mbarrier.try_wait.parity.shared.b64 p, [%1], %2; "
                         "selp.b32 %0, 1, 0, p; }"
                         : "=r"(done) : "r"(mbar), "r"(phase) : "memory");
        } while (!done);
        phase ^= 1;

        asm volatile("cp.async.bulk.global.shared::cta.bulk_group [%0], [%1], %2;"
                     :: "l"(dst), "r"(buf), "r"(n) : "memory");
        asm volatile("cp.async.bulk.commit_group;" ::: "memory");
        asm volatile("cp.async.bulk.wait_group 0;" ::: "memory");

        p0 += nn;
    }
}

// ---------------------------------------------------------------------------
// Fused kernel: period-33 block striping (9 hash / 16 lidar / 8 copy).
// ---------------------------------------------------------------------------
__global__ void __launch_bounds__(256, 3)
fused_kernel(Args A)
{
    extern __shared__ float sm[];
    const int b = blockIdx.x;
    const int period = b / 33;
    const int r = b - period * 33;

    if (r < 9) {
        hash_part(period * 9 + r, A, sm);
    } else if (r < 25) {
        lidar_part(period * 16 + (r - 9), A, sm);
    } else {
        copy_part(period * 8 + (r - 25), A, sm);
    }
}

// ---------------------------------------------------------------------------
// Launch
// ---------------------------------------------------------------------------
extern "C" void kernel_launch(void* const* d_in, const int* in_sizes, int n_in,
                              void* d_out, int out_size)
{
    (void)in_sizes; (void)n_in; (void)out_size;

    static bool attr_done = false;
    if (!attr_done) {
        cudaFuncSetAttribute(fused_kernel,
                             cudaFuncAttributeMaxDynamicSharedMemorySize, SMEM_BYTES);
        attr_done = true;
    }

    Args A;
    for (int i = 0; i < 30; i++) A.p[i] = (const float*)d_in[i];
    A.out = (float*)d_out;

    fused_kernel<<<GRID_BLKS, 256, SMEM_BYTES>>>(A);
}